// round 17
// baseline (speedup 1.0000x reference)
#include <cuda_runtime.h>
#include <cuda_fp16.h>
#include <cstdint>

typedef uint32_t u32;

// ---- sigmoid LUT config: z in [-8, 8], nearest-neighbor ----
#define SIG_N 12160
#define SIG_S 760.0f     // entries per z-unit
#define SIG_C 6080.0f    // center offset

// ---- f16x2 helpers ----
__device__ __forceinline__ u32 pk16(float lo, float hi) {  // lo -> low half
    u32 r; asm("cvt.rn.f16x2.f32 %0, %1, %2;" : "=r"(r) : "f"(hi), "f"(lo)); return r;
}
__device__ __forceinline__ void up16(u32 p, float& lo, float& hi) {
    asm("{ .reg .b16 l, h; mov.b32 {l, h}, %2; cvt.f32.f16 %0, l; cvt.f32.f16 %1, h; }"
        : "=f"(lo), "=f"(hi) : "r"(p));
}
__device__ __forceinline__ u32 th2(u32 x) {                // 2x tanh, 1 MUFU op
    u32 r; asm("tanh.approx.f16x2 %0, %1;" : "=r"(r) : "r"(x)); return r;
}
__device__ __forceinline__ u32 hmul2(u32 a, u32 b) {
    u32 r; asm("mul.rn.f16x2 %0, %1, %2;" : "=r"(r) : "r"(a), "r"(b)); return r;
}

// m16n8k16 f16 inputs, f32 D/C (bias rides exactly in C)
__device__ __forceinline__ void mma_f(float* d,
                                      u32 a0, u32 a1, u32 a2, u32 a3,
                                      u32 b0, u32 b1,
                                      float c0, float c1, float c2, float c3) {
    asm("mma.sync.aligned.m16n8k16.row.col.f32.f16.f16.f32 "
        "{%0,%1,%2,%3}, {%4,%5,%6,%7}, {%8,%9}, {%10,%11,%12,%13};"
        : "=f"(d[0]), "=f"(d[1]), "=f"(d[2]), "=f"(d[3])
        : "r"(a0), "r"(a1), "r"(a2), "r"(a3), "r"(b0), "r"(b1),
          "f"(c0), "f"(c1), "f"(c2), "f"(c3));
}
// m16n8k16 all-f16 (g-gate: D feeds tanh.f16x2 directly)
__device__ __forceinline__ void mma_h(u32& d0, u32& d1,
                                      u32 a0, u32 a1, u32 a2, u32 a3,
                                      u32 b0, u32 b1, u32 c0, u32 c1) {
    asm("mma.sync.aligned.m16n8k16.row.col.f16.f16.f16.f16 "
        "{%0,%1}, {%2,%3,%4,%5}, {%6,%7}, {%8,%9};"
        : "=r"(d0), "=r"(d1)
        : "r"(a0), "r"(a1), "r"(a2), "r"(a3), "r"(b0), "r"(b1), "r"(c0), "r"(c1));
}

// One warp = 16 sequences. MUFU off-load design:
//   i,f,o gates: f32-D MMA -> sigmoid via shared-mem LUT (fma/alu/LSU pipes)
//   g gate:      f16-D MMA -> tanh.approx.f16x2 (MUFU)
//   c:           f32 state; tanh(c) via f16x2 MUFU
// MUFU evals/thread-step: 40 -> 16 (the invariant wall across R6-R16).
// Deep pipeline: A issue L1(t); B consume L0(t+1); C issue L0(t+2); D consume L1(t).
__global__ void __launch_bounds__(128) lstm_lut(
    const float* __restrict__ input,
    const float* __restrict__ w_ih0, const float* __restrict__ w_hh0,
    const float* __restrict__ b_ih0, const float* __restrict__ b_hh0,
    const float* __restrict__ w_ih1, const float* __restrict__ w_hh1,
    const float* __restrict__ b_ih1, const float* __restrict__ b_hh1,
    const float* __restrict__ w_mlp, const float* __restrict__ b_mlp,
    float* __restrict__ out, int B)
{
    const int T = 256;
    __shared__ float sigt[SIG_N];

    int tid  = threadIdx.x;
    int lane = tid & 31;
    int gid  = lane >> 2;          // B-frag n index / D-A row group
    int tg   = lane & 3;           // k/col pair group
    int warp = (blockIdx.x * (blockDim.x >> 5)) + (tid >> 5);
    int wbase = warp * 16;

    // ---- build sigmoid table (one-time) ----
    for (int i = tid; i < SIG_N; i += 128) {
        float z = ((float)i - SIG_C) * (1.0f / SIG_S);
        sigt[i] = 1.0f / (1.0f + __expf(-z));
    }
    __syncthreads();

    int rA = wbase + gid;
    int rB = wbase + gid + 8;
    int rAc = (rA < B) ? rA : (B - 1);
    int rBc = (rB < B) ? rB : (B - 1);

    // ---- weights: single-f16 B fragments, unprescaled ----
    // per gate: b0 = (n=gid, k=2tg,2tg+1), b1 = (n=gid, k=8+2tg,9+2tg)
    u32 B0a[4], B0b[4], B1a[4], B1b[4];
    float be0[4], bo0[4], be1[4], bo1[4];   // f32 biases (i,f,o exact; g unused slot)
    u32 cbg0, cbg1;                         // g-gate f16x2 biases (L0, L1)
#pragma unroll
    for (int g = 0; g < 4; g++) {
        int wr = g * 8 + gid;
        // L0: k0-7 = w_hh0; k8,9 = w_ih0 (tg==0), rest 0
        B0a[g] = pk16(w_hh0[wr * 8 + 2 * tg], w_hh0[wr * 8 + 2 * tg + 1]);
        float v0 = 0.f, v1 = 0.f;
        if (tg == 0) { v0 = w_ih0[wr * 2]; v1 = w_ih0[wr * 2 + 1]; }
        B0b[g] = pk16(v0, v1);
        // L1: k0-7 = w_ih1 (vs h0); k8-15 = w_hh1 (vs h1)
        B1a[g] = pk16(w_ih1[wr * 8 + 2 * tg], w_ih1[wr * 8 + 2 * tg + 1]);
        B1b[g] = pk16(w_hh1[wr * 8 + 2 * tg], w_hh1[wr * 8 + 2 * tg + 1]);
        // biases (D cols 2tg, 2tg+1)
        int cE = g * 8 + 2 * tg;
        be0[g] = b_ih0[cE] + b_hh0[cE];
        bo0[g] = b_ih0[cE + 1] + b_hh0[cE + 1];
        be1[g] = b_ih1[cE] + b_hh1[cE];
        bo1[g] = b_ih1[cE + 1] + b_hh1[cE + 1];
    }
    cbg0 = pk16(be0[2], bo0[2]);
    cbg1 = pk16(be1[2], bo1[2]);

    // ---- sigmoid via LUT ----
    auto lut = [&](float z) -> float {
        u32 idx = __float2uint_rn(fmaf(z, SIG_S, SIG_C));  // negatives clamp to 0
        idx = min(idx, (u32)(SIG_N - 1));
        return sigt[idx];
    };

    // ---- state ----
    float c0[4] = {0.f, 0.f, 0.f, 0.f};
    float c1[4] = {0.f, 0.f, 0.f, 0.f};
    u32 h0p0 = 0, h0p1 = 0, h1p0 = 0, h1p1 = 0;
    // L0 accumulators: i,f,o f32-D; g f16-D
    float dI0[4], dF0[4], dO0[4];
    u32 g0a, g0b;
    // L1 accumulators
    float dI1[4], dF1[4], dO1[4];
    u32 g1a, g1b;

    const float2* xr = reinterpret_cast<const float2*>(input);
    auto xsel = [&](float2 x) -> u32 { return (tg == 0) ? pk16(x.x, x.y) : 0u; };

    // cell consume: i,f,o f32 preacts (LUT), g f16 pack (th2), c f32, h f16x2
    auto cell = [&](float* dI, float* dF, float* dO, u32 ga, u32 gb,
                    float* c, u32& hp0, u32& hp1) {
        u32 tg0 = th2(ga), tg1 = th2(gb);
        float gv0, gv1, gv2, gv3;
        up16(tg0, gv0, gv1);
        up16(tg1, gv2, gv3);
        float i0 = lut(dI[0]), i1 = lut(dI[1]), i2 = lut(dI[2]), i3 = lut(dI[3]);
        float f0 = lut(dF[0]), f1 = lut(dF[1]), f2 = lut(dF[2]), f3 = lut(dF[3]);
        float o0 = lut(dO[0]), o1 = lut(dO[1]), o2 = lut(dO[2]), o3 = lut(dO[3]);
        c[0] = fmaf(f0, c[0], i0 * gv0);
        c[1] = fmaf(f1, c[1], i1 * gv1);
        c[2] = fmaf(f2, c[2], i2 * gv2);
        c[3] = fmaf(f3, c[3], i3 * gv3);
        u32 tc0 = th2(pk16(c[0], c[1]));
        u32 tc1 = th2(pk16(c[2], c[3]));
        hp0 = hmul2(pk16(o0, o1), tc0);
        hp1 = hmul2(pk16(o2, o3), tc1);
    };

    auto issueL0 = [&](u32 xa2, u32 xa3, u32 a0, u32 a1) {
        mma_f(dI0, a0, a1, xa2, xa3, B0a[0], B0b[0], be0[0], bo0[0], be0[0], bo0[0]);
        mma_f(dF0, a0, a1, xa2, xa3, B0a[1], B0b[1], be0[1], bo0[1], be0[1], bo0[1]);
        mma_h(g0a, g0b, a0, a1, xa2, xa3, B0a[2], B0b[2], cbg0, cbg0);
        mma_f(dO0, a0, a1, xa2, xa3, B0a[3], B0b[3], be0[3], bo0[3], be0[3], bo0[3]);
    };

    // ---- prologue ----
    {
        float2 xA = __ldg(&xr[(size_t)rAc * T]);
        float2 xB = __ldg(&xr[(size_t)rBc * T]);
        issueL0(xsel(xA), xsel(xB), 0u, 0u);         // L0(0), h0(-1)=0
        cell(dI0, dF0, dO0, g0a, g0b, c0, h0p0, h0p1);
        xA = __ldg(&xr[(size_t)rAc * T + 1]);
        xB = __ldg(&xr[(size_t)rBc * T + 1]);
        issueL0(xsel(xA), xsel(xB), h0p0, h0p1);     // L0(1)
    }

    for (int t = 0; t < T; t++) {
        // ---- A: issue L1(t) using h0(t), h1(t-1) ----
        mma_f(dI1, h0p0, h0p1, h1p0, h1p1, B1a[0], B1b[0], be1[0], bo1[0], be1[0], bo1[0]);
        mma_f(dF1, h0p0, h0p1, h1p0, h1p1, B1a[1], B1b[1], be1[1], bo1[1], be1[1], bo1[1]);
        mma_h(g1a, g1b, h0p0, h0p1, h1p0, h1p1, B1a[2], B1b[2], cbg1, cbg1);
        mma_f(dO1, h0p0, h0p1, h1p0, h1p1, B1a[3], B1b[3], be1[3], bo1[3], be1[3], bo1[3]);

        // ---- B: consume L0(t+1) -> h0(t+1)  (covers A's MMA latency) ----
        cell(dI0, dF0, dO0, g0a, g0b, c0, h0p0, h0p1);

        // ---- C: issue L0(t+2) using h0(t+1) ----
        {
            int tn = (t + 2 < T) ? (t + 2) : (T - 1);
            float2 xA = __ldg(&xr[(size_t)rAc * T + tn]);
            float2 xB = __ldg(&xr[(size_t)rBc * T + tn]);
            issueL0(xsel(xA), xsel(xB), h0p0, h0p1);
        }

        // ---- D: consume L1(t) -> h1(t) ----
        cell(dI1, dF1, dO1, g1a, g1b, c1, h1p0, h1p1);
    }

    // ================= MLP head (h1 from f16 packs) =================
    float h1f[4];
    up16(h1p0, h1f[0], h1f[1]);
    up16(h1p1, h1f[2], h1f[3]);
    int hidE = tg * 2;
    float w0e = w_mlp[hidE],     w0o = w_mlp[hidE + 1];
    float w1e = w_mlp[8 + hidE], w1o = w_mlp[8 + hidE + 1];
    float p0A = h1f[0] * w0e + h1f[1] * w0o;
    float p1A = h1f[0] * w1e + h1f[1] * w1o;
    float p0B = h1f[2] * w0e + h1f[3] * w0o;
    float p1B = h1f[2] * w1e + h1f[3] * w1o;
#pragma unroll
    for (int off = 1; off < 4; off <<= 1) {
        p0A += __shfl_xor_sync(0xffffffffu, p0A, off);
        p1A += __shfl_xor_sync(0xffffffffu, p1A, off);
        p0B += __shfl_xor_sync(0xffffffffu, p0B, off);
        p1B += __shfl_xor_sync(0xffffffffu, p1B, off);
    }
    if (tg == 0) {
        if (rA < B) {
            float2 o; o.x = p0A + b_mlp[0]; o.y = p1A + b_mlp[1];
            reinterpret_cast<float2*>(out)[rA] = o;
        }
        if (rB < B) {
            float2 o; o.x = p0B + b_mlp[0]; o.y = p1B + b_mlp[1];
            reinterpret_cast<float2*>(out)[rB] = o;
        }
    }
}

extern "C" void kernel_launch(void* const* d_in, const int* in_sizes, int n_in,
                              void* d_out, int out_size) {
    const float* input = (const float*)d_in[0];
    const float* w_ih0 = (const float*)d_in[1];
    const float* w_hh0 = (const float*)d_in[2];
    const float* b_ih0 = (const float*)d_in[3];
    const float* b_hh0 = (const float*)d_in[4];
    const float* w_ih1 = (const float*)d_in[5];
    const float* w_hh1 = (const float*)d_in[6];
    const float* b_ih1 = (const float*)d_in[7];
    const float* b_hh1 = (const float*)d_in[8];
    const float* w_mlp = (const float*)d_in[9];
    const float* b_mlp = (const float*)d_in[10];

    const int T = 256, IN = 2;
    int B = in_sizes[0] / (T * IN);

    int grid = (B + 63) / 64;      // 16 seqs/warp, 4 warps/block
    lstm_lut<<<grid, 128>>>(input, w_ih0, w_hh0, b_ih0, b_hh0,
                            w_ih1, w_hh1, b_ih1, b_hh1,
                            w_mlp, b_mlp, (float*)d_out, B);
}